// round 1
// baseline (speedup 1.0000x reference)
#include <cuda_runtime.h>

#define NN 20000
#define NE 320000
#define NG 512
#define BN_CHUNKS 10

// ---------------- scratch (device globals; no allocation allowed) ----------
__device__ float g_bufA[NN * 1024];
__device__ float g_bufB[NN * 1024];
__device__ float g_deg[NN];
__device__ float g_dinv[NN];
__device__ float g_enorm[NE];
__device__ float g_mean[1024];
__device__ float g_rstd[1024];
__device__ float g_ps[BN_CHUNKS * 1024];
__device__ float g_pq[BN_CHUNKS * 1024];
__device__ float g_gate[NN];
__device__ float g_gmax[NG];
__device__ float g_gsum[NG];
__device__ float g_pool[NG * 1024];
__device__ float g_p2[NG * 128];
__device__ float g_p3[NG * 16];

// ---------------- small utility kernels ------------------------------------
__global__ void k_fill(float* p, long n, float v) {
    long i = (long)blockIdx.x * blockDim.x + threadIdx.x;
    if (i < n) p[i] = v;
}

__global__ void k_deg(const int* __restrict__ col, float* __restrict__ deg) {
    int e = blockIdx.x * blockDim.x + threadIdx.x;
    if (e < NE) atomicAdd(&deg[col[e]], 1.0f);
}

__global__ void k_dinv(const float* __restrict__ deg, float* __restrict__ dinv) {
    int i = blockIdx.x * blockDim.x + threadIdx.x;
    if (i < NN) dinv[i] = rsqrtf(deg[i]);
}

__global__ void k_enorm(const int* __restrict__ row, const int* __restrict__ col,
                        const float* __restrict__ dinv, float* __restrict__ nrm) {
    int e = blockIdx.x * blockDim.x + threadIdx.x;
    if (e < NE) nrm[e] = dinv[row[e]] * dinv[col[e]];
}

// ---------------- aggregation: out = D^-1/2 (A+I) D^-1/2 @ src -------------
// self-loop term doubles as the initializer for dst
__global__ void k_aggself(const float* __restrict__ src, float* __restrict__ dst,
                          const float* __restrict__ dinv, long tot, int F) {
    long i = (long)blockIdx.x * blockDim.x + threadIdx.x;
    if (i >= tot) return;
    int v = (int)(i / F);
    float d = dinv[v];
    dst[i] = d * d * src[i];
}

__global__ void k_aggedge(const float* __restrict__ src, float* __restrict__ dst,
                          const int* __restrict__ row, const int* __restrict__ col,
                          const float* __restrict__ nrm, int F) {
    int e = blockIdx.x;
    float w = nrm[e];
    const float* s = src + (long)row[e] * F;
    float* d = dst + (long)col[e] * F;
    for (int f = threadIdx.x; f < F; f += blockDim.x)
        atomicAdd(&d[f], w * s[f]);
}

// ---------------- SGEMM: C[M,N] = A[M,K] @ W[K,N] (+bias, relu) ------------
__global__ __launch_bounds__(256) void k_gemm(
    const float* __restrict__ A, const float* __restrict__ W,
    const float* __restrict__ bias, float* __restrict__ C,
    int M, int N, int K, int doRelu)
{
    __shared__ float As[16][65];
    __shared__ float Bs[16][65];
    int bm = blockIdx.y * 64;
    int bn = blockIdx.x * 64;
    int tid = threadIdx.x;
    int tx = tid & 15, ty = tid >> 4;
    float acc[4][4] = {};

    for (int k0 = 0; k0 < K; k0 += 16) {
#pragma unroll
        for (int i = 0; i < 4; i++) {
            int idx = tid + i * 256;
            int r = idx >> 4, c = idx & 15;
            int gr = bm + r, gc = k0 + c;
            As[c][r] = (gr < M && gc < K) ? A[(long)gr * K + gc] : 0.0f;
        }
#pragma unroll
        for (int i = 0; i < 4; i++) {
            int idx = tid + i * 256;
            int r = idx >> 6, c = idx & 63;
            int gr = k0 + r, gc = bn + c;
            Bs[r][c] = (gr < K && gc < N) ? W[(long)gr * N + gc] : 0.0f;
        }
        __syncthreads();
#pragma unroll
        for (int k = 0; k < 16; k++) {
            float a[4], b[4];
#pragma unroll
            for (int i = 0; i < 4; i++) a[i] = As[k][ty * 4 + i];
#pragma unroll
            for (int j = 0; j < 4; j++) b[j] = Bs[k][tx * 4 + j];
#pragma unroll
            for (int i = 0; i < 4; i++)
#pragma unroll
                for (int j = 0; j < 4; j++) acc[i][j] += a[i] * b[j];
        }
        __syncthreads();
    }
#pragma unroll
    for (int i = 0; i < 4; i++) {
        int gr = bm + ty * 4 + i;
        if (gr >= M) continue;
#pragma unroll
        for (int j = 0; j < 4; j++) {
            int gc = bn + tx * 4 + j;
            float v = acc[i][j];
            if (bias) v += bias[gc];
            if (doRelu) v = fmaxf(v, 0.0f);
            C[(long)gr * N + gc] = v;
        }
    }
}

// ---------------- BatchNorm (training-mode, biased var), two pass ----------
// If bias != null, the normalized value is relu(x + bias[c]) (fuses GCN
// bias + relu of agg-last layers); otherwise x is used as-is.
__global__ void k_bnpart(const float* __restrict__ X, const float* __restrict__ bias,
                         int M, int N, float* __restrict__ ps, float* __restrict__ pq) {
    int lane = threadIdx.x & 31, ry = threadIdx.x >> 5;  // block 256 = 8x32
    int c = blockIdx.x * 32 + lane;
    int nch = gridDim.y;
    int per = (M + nch - 1) / nch;
    int r0 = blockIdx.y * per;
    int r1 = min(M, r0 + per);
    float s = 0.0f, q = 0.0f;
    if (c < N) {
        float bb = bias ? bias[c] : 0.0f;
        bool rl = (bias != nullptr);
        for (int r = r0 + ry; r < r1; r += 8) {
            float v = X[(long)r * N + c];
            if (rl) v = fmaxf(v + bb, 0.0f);
            s += v;
            q += v * v;
        }
    }
    __shared__ float sh[16][32];
    sh[ry][lane] = s;
    sh[8 + ry][lane] = q;
    __syncthreads();
    if (ry == 0 && c < N) {
#pragma unroll
        for (int i = 1; i < 8; i++) { s += sh[i][lane]; q += sh[8 + i][lane]; }
        ps[blockIdx.y * N + c] = s;
        pq[blockIdx.y * N + c] = q;
    }
}

__global__ void k_bnfin(const float* __restrict__ ps, const float* __restrict__ pq,
                        int N, int nch, float* __restrict__ mean, float* __restrict__ rstd) {
    int c = blockIdx.x * blockDim.x + threadIdx.x;
    if (c >= N) return;
    float s = 0.0f, q = 0.0f;
    for (int i = 0; i < nch; i++) { s += ps[i * N + c]; q += pq[i * N + c]; }
    float m = s / (float)NN;
    mean[c] = m;
    float var = q / (float)NN - m * m;
    rstd[c] = rsqrtf(fmaxf(var, 0.0f) + 1e-5f);
}

__global__ void k_bnapply(float* __restrict__ X, const float* __restrict__ bias,
                          const float* __restrict__ gm, const float* __restrict__ bt,
                          const float* __restrict__ mean, const float* __restrict__ rstd,
                          long tot, int N) {
    long i = (long)blockIdx.x * blockDim.x + threadIdx.x;
    if (i >= tot) return;
    int c = (int)(i % N);
    float v = X[i];
    if (bias) v = fmaxf(v + bias[c], 0.0f);
    X[i] = gm[c] * (v - mean[c]) * rstd[c] + bt[c];
}

// ---------------- global attention pooling ---------------------------------
__global__ void k_gate(const float* __restrict__ H, const float* __restrict__ Wg,
                       const float* __restrict__ bg, float* __restrict__ gate) {
    int t = blockIdx.x * blockDim.x + threadIdx.x;
    int v = t >> 5, lane = t & 31;
    if (v >= NN) return;
    const float* h = H + (long)v * 1024;
    float s = 0.0f;
    for (int k = lane; k < 1024; k += 32) s += h[k] * Wg[k];
#pragma unroll
    for (int o = 16; o; o >>= 1) s += __shfl_down_sync(0xffffffffu, s, o);
    if (lane == 0) gate[v] = s + bg[0];
}

__global__ void k_segmax(const float* __restrict__ gate, const int* __restrict__ batch,
                         float* __restrict__ gmax) {
    int i = blockIdx.x * blockDim.x + threadIdx.x;
    if (i >= NN) return;
    float v = gate[i];
    float* addr = &gmax[batch[i]];
    int old = __float_as_int(*addr);
    while (v > __int_as_float(old)) {
        int prev = atomicCAS((int*)addr, old, __float_as_int(v));
        if (prev == old) break;
        old = prev;
    }
}

__global__ void k_exps(float* __restrict__ gate, const int* __restrict__ batch,
                       const float* __restrict__ gmax, float* __restrict__ gsum) {
    int i = blockIdx.x * blockDim.x + threadIdx.x;
    if (i >= NN) return;
    int b = batch[i];
    float e = expf(gate[i] - gmax[b]);
    gate[i] = e;
    atomicAdd(&gsum[b], e);
}

__global__ void k_coef(float* __restrict__ gate, const int* __restrict__ batch,
                       const float* __restrict__ gsum) {
    int i = blockIdx.x * blockDim.x + threadIdx.x;
    if (i >= NN) return;
    gate[i] = gate[i] / gsum[batch[i]];
}

__global__ void k_pool(const float* __restrict__ H, const float* __restrict__ gate,
                       const int* __restrict__ batch, float* __restrict__ pool) {
    long i = (long)blockIdx.x * blockDim.x + threadIdx.x;
    if (i >= (long)NN * 1024) return;
    int v = (int)(i >> 10);
    int f = (int)(i & 1023);
    atomicAdd(&pool[((long)batch[v] << 10) + f], gate[v] * H[i]);
}

// ---------------- small MLP GEMMs ------------------------------------------
__global__ void k_mlp(const float* __restrict__ X, const float* __restrict__ W,
                      const float* __restrict__ bias, float* __restrict__ Y,
                      int M, int N, int K, int relu) {
    int i = blockIdx.x * blockDim.x + threadIdx.x;
    if (i >= M * N) return;
    int m = i / N, n = i % N;
    float s = bias[n];
    for (int k = 0; k < K; k++) s += X[m * K + k] * W[k * N + n];
    if (relu) s = fmaxf(s, 0.0f);
    Y[i] = s;
}

// ---------------- launch -----------------------------------------------------
extern "C" void kernel_launch(void* const* d_in, const int* in_sizes, int n_in,
                              void* d_out, int out_size) {
    (void)in_sizes; (void)n_in; (void)out_size;
    const float* x = (const float*)d_in[0];
    const int* ei = (const int*)d_in[1];
    const int* row = ei;
    const int* col = ei + NE;
    const int* batch = (const int*)d_in[2];
    const float *W[5], *b[5], *g[5], *be[5];
    for (int i = 0; i < 5; i++) {
        W[i]  = (const float*)d_in[3 + 4 * i];
        b[i]  = (const float*)d_in[4 + 4 * i];
        g[i]  = (const float*)d_in[5 + 4 * i];
        be[i] = (const float*)d_in[6 + 4 * i];
    }
    const float* Wg  = (const float*)d_in[23];
    const float* bg  = (const float*)d_in[24];
    const float* Wf2 = (const float*)d_in[25];
    const float* bf2 = (const float*)d_in[26];
    const float* Wf3 = (const float*)d_in[27];
    const float* bf3 = (const float*)d_in[28];
    const float* Wf4 = (const float*)d_in[29];
    const float* bf4 = (const float*)d_in[30];

    float *A, *B, *deg, *dinv, *nrm, *mean, *rstd, *ps, *pq;
    float *gate, *gmax, *gsum, *pool, *p2, *p3;
    cudaGetSymbolAddress((void**)&A, g_bufA);
    cudaGetSymbolAddress((void**)&B, g_bufB);
    cudaGetSymbolAddress((void**)&deg, g_deg);
    cudaGetSymbolAddress((void**)&dinv, g_dinv);
    cudaGetSymbolAddress((void**)&nrm, g_enorm);
    cudaGetSymbolAddress((void**)&mean, g_mean);
    cudaGetSymbolAddress((void**)&rstd, g_rstd);
    cudaGetSymbolAddress((void**)&ps, g_ps);
    cudaGetSymbolAddress((void**)&pq, g_pq);
    cudaGetSymbolAddress((void**)&gate, g_gate);
    cudaGetSymbolAddress((void**)&gmax, g_gmax);
    cudaGetSymbolAddress((void**)&gsum, g_gsum);
    cudaGetSymbolAddress((void**)&pool, g_pool);
    cudaGetSymbolAddress((void**)&p2, g_p2);
    cudaGetSymbolAddress((void**)&p3, g_p3);

    // ---- graph normalization (depends only on edge_index) ----
    k_fill<<<(NN + 255) / 256, 256>>>(deg, NN, 1.0f);            // self-loop
    k_deg<<<(NE + 255) / 256, 256>>>(col, deg);
    k_dinv<<<(NN + 255) / 256, 256>>>(deg, dinv);
    k_enorm<<<(NE + 255) / 256, 256>>>(row, col, dinv, nrm);

    auto agg = [&](const float* src, float* dst, int F) {
        long tot = (long)NN * F;
        k_aggself<<<(int)((tot + 255) / 256), 256>>>(src, dst, dinv, tot, F);
        int th = (F >= 256) ? 256 : ((F >= 64) ? 64 : 32);
        k_aggedge<<<NE, th>>>(src, dst, row, col, nrm, F);
    };
    auto gemm = [&](const float* Ain, const float* Win, const float* bias, float* C,
                    int M, int Nn, int K, int relu) {
        dim3 gr(Nn / 64, (M + 63) / 64);
        k_gemm<<<gr, 256>>>(Ain, Win, bias, C, M, Nn, K, relu);
    };
    auto bn = [&](float* X, const float* bias, const float* gm, const float* bt, int F) {
        dim3 gr((F + 31) / 32, BN_CHUNKS);
        k_bnpart<<<gr, 256>>>(X, bias, NN, F, ps, pq);
        k_bnfin<<<(F + 127) / 128, 128>>>(ps, pq, F, BN_CHUNKS, mean, rstd);
        long tot = (long)NN * F;
        k_bnapply<<<(int)((tot + 255) / 256), 256>>>(X, bias, gm, bt, mean, rstd, tot, F);
    };

    // Layer 1 (29 -> 1024): aggregate first (29 feats), then GEMM(+b,relu), BN
    agg(x, A, 29);
    gemm(A, W[0], b[0], B, NN, 1024, 29, 1);
    bn(B, nullptr, g[0], be[0], 1024);

    // Layer 2 (1024 -> 512): GEMM first, aggregate on 512, then b+relu+BN fused
    gemm(B, W[1], nullptr, A, NN, 512, 1024, 0);
    agg(A, B, 512);
    bn(B, b[1], g[1], be[1], 512);

    // Layer 3 (512 -> 256): GEMM first, aggregate on 256
    gemm(B, W[2], nullptr, A, NN, 256, 512, 0);
    agg(A, B, 256);
    bn(B, b[2], g[2], be[2], 256);

    // Layer 4 (256 -> 512): aggregate first (256), GEMM(+b,relu), BN
    agg(B, A, 256);
    gemm(A, W[3], b[3], B, NN, 512, 256, 1);
    bn(B, nullptr, g[3], be[3], 512);

    // Layer 5 (512 -> 1024): aggregate first (512), GEMM(+b,relu), BN
    agg(B, A, 512);
    gemm(A, W[4], b[4], B, NN, 1024, 512, 1);
    bn(B, nullptr, g[4], be[4], 1024);

    // ---- global attention pooling ----
    k_gate<<<(NN * 32 + 255) / 256, 256>>>(B, Wg, bg, gate);
    k_fill<<<(NG + 255) / 256, 256>>>(gmax, NG, -3e38f);
    k_fill<<<(NG + 255) / 256, 256>>>(gsum, NG, 0.0f);
    k_segmax<<<(NN + 255) / 256, 256>>>(gate, batch, gmax);
    k_exps<<<(NN + 255) / 256, 256>>>(gate, batch, gmax, gsum);
    k_coef<<<(NN + 255) / 256, 256>>>(gate, batch, gsum);
    k_fill<<<(NG * 1024 + 255) / 256, 256>>>(pool, (long)NG * 1024, 0.0f);
    k_pool<<<(int)(((long)NN * 1024 + 255) / 256), 256>>>(B, gate, batch, pool);

    // ---- MLP head ----
    k_mlp<<<(NG * 128 + 255) / 256, 256>>>(pool, Wf2, bf2, p2, NG, 128, 1024, 1);
    k_mlp<<<(NG * 16 + 255) / 256, 256>>>(p2, Wf3, bf3, p3, NG, 16, 128, 1);
    k_mlp<<<(NG + 255) / 256, 256>>>(p3, Wf4, bf4, (float*)d_out, NG, 1, 16, 0);
}

// round 4
// speedup vs baseline: 1.6656x; 1.6656x over previous
#include <cuda_runtime.h>
#include <cstdint>

#define NN 20000
#define NE 320000
#define NG 512
#define BN_CHUNKS 10

// ---------------- scratch (device globals; no allocation allowed) ----------
__device__ float g_bufA[NN * 1024];
__device__ float g_bufB[NN * 1024];
__device__ float g_deg[NN];
__device__ float g_dinv[NN];
__device__ float g_enorm[NE];
__device__ float g_mean[1024];
__device__ float g_rstd[1024];
__device__ float g_ps[BN_CHUNKS * 1024];
__device__ float g_pq[BN_CHUNKS * 1024];
__device__ float g_gate[NN];
__device__ float g_gmax[NG];
__device__ float g_gsum[NG];
__device__ float g_pool[NG * 1024];
__device__ float g_p2[NG * 128];
__device__ float g_p3[NG * 16];

// ---------------- small utility kernels ------------------------------------
__global__ void k_fill(float* p, long n, float v) {
    long i = (long)blockIdx.x * blockDim.x + threadIdx.x;
    if (i < n) p[i] = v;
}

__global__ void k_deg(const int* __restrict__ col, float* __restrict__ deg) {
    int e = blockIdx.x * blockDim.x + threadIdx.x;
    if (e < NE) atomicAdd(&deg[col[e]], 1.0f);
}

__global__ void k_dinv(const float* __restrict__ deg, float* __restrict__ dinv) {
    int i = blockIdx.x * blockDim.x + threadIdx.x;
    if (i < NN) dinv[i] = rsqrtf(deg[i]);
}

__global__ void k_enorm(const int* __restrict__ row, const int* __restrict__ col,
                        const float* __restrict__ dinv, float* __restrict__ nrm) {
    int e = blockIdx.x * blockDim.x + threadIdx.x;
    if (e < NE) nrm[e] = dinv[row[e]] * dinv[col[e]];
}

// ---------------- aggregation: out = D^-1/2 (A+I) D^-1/2 @ src -------------
__global__ void k_aggself(const float* __restrict__ src, float* __restrict__ dst,
                          const float* __restrict__ dinv, long tot, int F) {
    long i = (long)blockIdx.x * blockDim.x + threadIdx.x;
    if (i >= tot) return;
    int v = (int)(i / F);
    float d = dinv[v];
    dst[i] = d * d * src[i];
}

// warp per edge, 8 edges per 256-thread block
__global__ void k_aggedge(const float* __restrict__ src, float* __restrict__ dst,
                          const int* __restrict__ row, const int* __restrict__ col,
                          const float* __restrict__ nrm, int F) {
    int e = blockIdx.x * (blockDim.x >> 5) + (threadIdx.x >> 5);
    if (e >= NE) return;
    int lane = threadIdx.x & 31;
    float w = nrm[e];
    const float* s = src + (long)row[e] * F;
    float* d = dst + (long)col[e] * F;
    for (int f = lane; f < F; f += 32)
        atomicAdd(&d[f], w * s[f]);
}

// ---------------- 3xTF32 tensor-core GEMM ----------------------------------
// C[M,N] = A[M,K] @ W[K,N] (+bias, relu). N multiple of 128. Block 128x128,
// 8 warps of 64x32, mma.sync m16n8k8 tf32 with hi/lo error compensation
// (acc += hi*hi + lo*hi + hi*lo), BK=16 double-buffered.
__device__ __forceinline__ void tf32split(float x, uint32_t& hi, uint32_t& lo) {
    uint32_t h;
    asm("cvt.rna.tf32.f32 %0, %1;" : "=r"(h) : "f"(x));
    float r = x - __uint_as_float(h);
    uint32_t l;
    asm("cvt.rna.tf32.f32 %0, %1;" : "=r"(l) : "f"(r));
    hi = h;
    lo = l;
}

__device__ __forceinline__ void mma_tf32(float* d, const uint32_t* a, const uint32_t* b) {
    asm volatile(
        "mma.sync.aligned.m16n8k8.row.col.f32.tf32.tf32.f32 "
        "{%0,%1,%2,%3}, {%4,%5,%6,%7}, {%8,%9}, {%0,%1,%2,%3};"
        : "+f"(d[0]), "+f"(d[1]), "+f"(d[2]), "+f"(d[3])
        : "r"(a[0]), "r"(a[1]), "r"(a[2]), "r"(a[3]), "r"(b[0]), "r"(b[1]));
}

__global__ __launch_bounds__(256) void k_gemm_tf32x3(
    const float* __restrict__ A, const float* __restrict__ W,
    const float* __restrict__ bias, float* __restrict__ C,
    int M, int N, int K, int doRelu)
{
    __shared__ float As[2][16][132];
    __shared__ float Bs[2][16][132];
    const int tid = threadIdx.x;
    const int warp = tid >> 5, lane = tid & 31;
    const int wm = warp >> 2, wn = warp & 3;
    const int gr = lane >> 2, gk = lane & 3;
    const int bm = blockIdx.y * 128, bn = blockIdx.x * 128;

    float acc[4][4][4];
#pragma unroll
    for (int i = 0; i < 4; i++)
#pragma unroll
        for (int j = 0; j < 4; j++)
#pragma unroll
            for (int r = 0; r < 4; r++) acc[i][j][r] = 0.0f;

    const int nc = (K + 15) / 16;
    const bool vec = (K & 15) == 0;

    const int ar = tid >> 2, aq = tid & 3;         // A: rows ar, ar+64; quad aq
    const int wr = tid >> 5, wc = (tid & 31) * 4;  // W: rows wr, wr+8

    float ra[8];
    float rb[8];

    auto fetch = [&](int c) {
        int k0 = c * 16;
        if (vec) {
            int g0 = bm + ar, g1 = bm + ar + 64;
            if (g0 < M) {
                float4 v = *(const float4*)(A + (long)g0 * K + k0 + aq * 4);
                ra[0] = v.x; ra[1] = v.y; ra[2] = v.z; ra[3] = v.w;
            } else ra[0] = ra[1] = ra[2] = ra[3] = 0.0f;
            if (g1 < M) {
                float4 v = *(const float4*)(A + (long)g1 * K + k0 + aq * 4);
                ra[4] = v.x; ra[5] = v.y; ra[6] = v.z; ra[7] = v.w;
            } else ra[4] = ra[5] = ra[6] = ra[7] = 0.0f;
        } else {
#pragma unroll
            for (int h = 0; h < 2; h++) {
                int g = bm + ar + h * 64;
#pragma unroll
                for (int q = 0; q < 4; q++) {
                    int kk = k0 + aq * 4 + q;
                    ra[h * 4 + q] = (g < M && kk < K) ? A[(long)g * K + kk] : 0.0f;
                }
            }
        }
#pragma unroll
        for (int h = 0; h < 2; h++) {
            int kk = k0 + wr + h * 8;
            if (kk < K) {
                float4 v = *(const float4*)(W + (long)kk * N + bn + wc);
                rb[h * 4 + 0] = v.x; rb[h * 4 + 1] = v.y;
                rb[h * 4 + 2] = v.z; rb[h * 4 + 3] = v.w;
            } else rb[h * 4 + 0] = rb[h * 4 + 1] = rb[h * 4 + 2] = rb[h * 4 + 3] = 0.0f;
        }
    };
    auto stage = [&](int buf) {
#pragma unroll
        for (int h = 0; h < 2; h++)
#pragma unroll
            for (int q = 0; q < 4; q++)
                As[buf][aq * 4 + q][ar + h * 64] = ra[h * 4 + q];
#pragma unroll
        for (int h = 0; h < 2; h++) {
            float* p = &Bs[buf][wr + h * 8][wc];
            p[0] = rb[h * 4 + 0];
            p[1] = rb[h * 4 + 1];
            p[2] = rb[h * 4 + 2];
            p[3] = rb[h * 4 + 3];
        }
    };

    fetch(0);
    stage(0);
    __syncthreads();

    for (int c = 0; c < nc; c++) {
        int buf = c & 1;
        if (c + 1 < nc) fetch(c + 1);
#pragma unroll
        for (int kk = 0; kk < 2; kk++) {
            uint32_t ah[4][4], al[4][4], bh[4][2], bl[4][2];
#pragma unroll
            for (int i = 0; i < 4; i++) {
                int m = wm * 64 + i * 16 + gr;
                tf32split(As[buf][kk * 8 + gk][m],      ah[i][0], al[i][0]);
                tf32split(As[buf][kk * 8 + gk][m + 8],  ah[i][1], al[i][1]);
                tf32split(As[buf][kk * 8 + gk + 4][m],      ah[i][2], al[i][2]);
                tf32split(As[buf][kk * 8 + gk + 4][m + 8],  ah[i][3], al[i][3]);
            }
#pragma unroll
            for (int j = 0; j < 4; j++) {
                int n = wn * 32 + j * 8 + gr;
                tf32split(Bs[buf][kk * 8 + gk][n],     bh[j][0], bl[j][0]);
                tf32split(Bs[buf][kk * 8 + gk + 4][n], bh[j][1], bl[j][1]);
            }
#pragma unroll
            for (int i = 0; i < 4; i++)
#pragma unroll
                for (int j = 0; j < 4; j++) {
                    mma_tf32(acc[i][j], al[i], bh[j]);   // lo*hi
                    mma_tf32(acc[i][j], ah[i], bl[j]);   // hi*lo
                    mma_tf32(acc[i][j], ah[i], bh[j]);   // hi*hi
                }
        }
        if (c + 1 < nc) {
            stage((c + 1) & 1);
        }
        __syncthreads();
    }

    // epilogue
#pragma unroll
    for (int i = 0; i < 4; i++) {
        int r0 = bm + wm * 64 + i * 16 + gr;
        int r1 = r0 + 8;
#pragma unroll
        for (int j = 0; j < 4; j++) {
            int cc = bn + wn * 32 + j * 8 + gk * 2;
            float b0 = bias ? bias[cc] : 0.0f;
            float b1 = bias ? bias[cc + 1] : 0.0f;
            float v0 = acc[i][j][0] + b0, v1 = acc[i][j][1] + b1;
            float v2 = acc[i][j][2] + b0, v3 = acc[i][j][3] + b1;
            if (doRelu) {
                v0 = fmaxf(v0, 0.0f); v1 = fmaxf(v1, 0.0f);
                v2 = fmaxf(v2, 0.0f); v3 = fmaxf(v3, 0.0f);
            }
            if (r0 < M) *(float2*)(C + (long)r0 * N + cc) = make_float2(v0, v1);
            if (r1 < M) *(float2*)(C + (long)r1 * N + cc) = make_float2(v2, v3);
        }
    }
}

// ---------------- BatchNorm (training-mode, biased var), two pass ----------
__global__ void k_bnpart(const float* __restrict__ X, const float* __restrict__ bias,
                         int M, int N, float* __restrict__ ps, float* __restrict__ pq) {
    int lane = threadIdx.x & 31, ry = threadIdx.x >> 5;  // block 256 = 8x32
    int c = blockIdx.x * 32 + lane;
    int nch = gridDim.y;
    int per = (M + nch - 1) / nch;
    int r0 = blockIdx.y * per;
    int r1 = min(M, r0 + per);
    float s = 0.0f, q = 0.0f;
    if (c < N) {
        float bb = bias ? bias[c] : 0.0f;
        bool rl = (bias != nullptr);
        for (int r = r0 + ry; r < r1; r += 8) {
            float v = X[(long)r * N + c];
            if (rl) v = fmaxf(v + bb, 0.0f);
            s += v;
            q += v * v;
        }
    }
    __shared__ float sh[16][32];
    sh[ry][lane] = s;
    sh[8 + ry][lane] = q;
    __syncthreads();
    if (ry == 0 && c < N) {
#pragma unroll
        for (int i = 1; i < 8; i++) { s += sh[i][lane]; q += sh[8 + i][lane]; }
        ps[blockIdx.y * N + c] = s;
        pq[blockIdx.y * N + c] = q;
    }
}

__global__ void k_bnfin(const float* __restrict__ ps, const float* __restrict__ pq,
                        int N, int nch, float* __restrict__ mean, float* __restrict__ rstd) {
    int c = blockIdx.x * blockDim.x + threadIdx.x;
    if (c >= N) return;
    float s = 0.0f, q = 0.0f;
    for (int i = 0; i < nch; i++) { s += ps[i * N + c]; q += pq[i * N + c]; }
    float m = s / (float)NN;
    mean[c] = m;
    float var = q / (float)NN - m * m;
    rstd[c] = rsqrtf(fmaxf(var, 0.0f) + 1e-5f);
}

__global__ void k_bnapply(float* __restrict__ X, const float* __restrict__ bias,
                          const float* __restrict__ gm, const float* __restrict__ bt,
                          const float* __restrict__ mean, const float* __restrict__ rstd,
                          long tot, int N) {
    long i = (long)blockIdx.x * blockDim.x + threadIdx.x;
    if (i >= tot) return;
    int c = (int)(i % N);
    float v = X[i];
    if (bias) v = fmaxf(v + bias[c], 0.0f);
    X[i] = gm[c] * (v - mean[c]) * rstd[c] + bt[c];
}

// ---------------- global attention pooling ---------------------------------
__global__ void k_gate(const float* __restrict__ H, const float* __restrict__ Wg,
                       const float* __restrict__ bg, float* __restrict__ gate) {
    int t = blockIdx.x * blockDim.x + threadIdx.x;
    int v = t >> 5, lane = t & 31;
    if (v >= NN) return;
    const float* h = H + (long)v * 1024;
    float s = 0.0f;
    for (int k = lane; k < 1024; k += 32) s += h[k] * Wg[k];
#pragma unroll
    for (int o = 16; o; o >>= 1) s += __shfl_down_sync(0xffffffffu, s, o);
    if (lane == 0) gate[v] = s + bg[0];
}

__global__ void k_segmax(const float* __restrict__ gate, const int* __restrict__ batch,
                         float* __restrict__ gmax) {
    int i = blockIdx.x * blockDim.x + threadIdx.x;
    if (i >= NN) return;
    float v = gate[i];
    float* addr = &gmax[batch[i]];
    int old = __float_as_int(*addr);
    while (v > __int_as_float(old)) {
        int prev = atomicCAS((int*)addr, old, __float_as_int(v));
        if (prev == old) break;
        old = prev;
    }
}

__global__ void k_exps(float* __restrict__ gate, const int* __restrict__ batch,
                       const float* __restrict__ gmax, float* __restrict__ gsum) {
    int i = blockIdx.x * blockDim.x + threadIdx.x;
    if (i >= NN) return;
    int b = batch[i];
    float e = expf(gate[i] - gmax[b]);
    gate[i] = e;
    atomicAdd(&gsum[b], e);
}

__global__ void k_coef(float* __restrict__ gate, const int* __restrict__ batch,
                       const float* __restrict__ gsum) {
    int i = blockIdx.x * blockDim.x + threadIdx.x;
    if (i >= NN) return;
    gate[i] = gate[i] / gsum[batch[i]];
}

__global__ void k_pool(const float* __restrict__ H, const float* __restrict__ gate,
                       const int* __restrict__ batch, float* __restrict__ pool) {
    long i = (long)blockIdx.x * blockDim.x + threadIdx.x;
    if (i >= (long)NN * 1024) return;
    int v = (int)(i >> 10);
    int f = (int)(i & 1023);
    atomicAdd(&pool[((long)batch[v] << 10) + f], gate[v] * H[i]);
}

// ---------------- small MLP GEMMs ------------------------------------------
__global__ void k_mlp(const float* __restrict__ X, const float* __restrict__ W,
                      const float* __restrict__ bias, float* __restrict__ Y,
                      int M, int N, int K, int relu) {
    int i = blockIdx.x * blockDim.x + threadIdx.x;
    if (i >= M * N) return;
    int m = i / N, n = i % N;
    float s = bias[n];
    for (int k = 0; k < K; k++) s += X[m * K + k] * W[k * N + n];
    if (relu) s = fmaxf(s, 0.0f);
    Y[i] = s;
}

// ---------------- launch -----------------------------------------------------
extern "C" void kernel_launch(void* const* d_in, const int* in_sizes, int n_in,
                              void* d_out, int out_size) {
    (void)in_sizes; (void)n_in; (void)out_size;
    const float* x = (const float*)d_in[0];
    const int* ei = (const int*)d_in[1];
    const int* row = ei;
    const int* col = ei + NE;
    const int* batch = (const int*)d_in[2];
    const float *W[5], *b[5], *g[5], *be[5];
    for (int i = 0; i < 5; i++) {
        W[i]  = (const float*)d_in[3 + 4 * i];
        b[i]  = (const float*)d_in[4 + 4 * i];
        g[i]  = (const float*)d_in[5 + 4 * i];
        be[i] = (const float*)d_in[6 + 4 * i];
    }
    const float* Wg  = (const float*)d_in[23];
    const float* bg  = (const float*)d_in[24];
    const float* Wf2 = (const float*)d_in[25];
    const float* bf2 = (const float*)d_in[26];
    const float* Wf3 = (const float*)d_in[27];
    const float* bf3 = (const float*)d_in[28];
    const float* Wf4 = (const float*)d_in[29];
    const float* bf4 = (const float*)d_in[30];

    float *A, *B, *deg, *dinv, *nrm, *mean, *rstd, *ps, *pq;
    float *gate, *gmax, *gsum, *pool, *p2, *p3;
    cudaGetSymbolAddress((void**)&A, g_bufA);
    cudaGetSymbolAddress((void**)&B, g_bufB);
    cudaGetSymbolAddress((void**)&deg, g_deg);
    cudaGetSymbolAddress((void**)&dinv, g_dinv);
    cudaGetSymbolAddress((void**)&nrm, g_enorm);
    cudaGetSymbolAddress((void**)&mean, g_mean);
    cudaGetSymbolAddress((void**)&rstd, g_rstd);
    cudaGetSymbolAddress((void**)&ps, g_ps);
    cudaGetSymbolAddress((void**)&pq, g_pq);
    cudaGetSymbolAddress((void**)&gate, g_gate);
    cudaGetSymbolAddress((void**)&gmax, g_gmax);
    cudaGetSymbolAddress((void**)&gsum, g_gsum);
    cudaGetSymbolAddress((void**)&pool, g_pool);
    cudaGetSymbolAddress((void**)&p2, g_p2);
    cudaGetSymbolAddress((void**)&p3, g_p3);

    // ---- graph normalization (depends only on edge_index) ----
    k_fill<<<(NN + 255) / 256, 256>>>(deg, NN, 1.0f);            // self-loop
    k_deg<<<(NE + 255) / 256, 256>>>(col, deg);
    k_dinv<<<(NN + 255) / 256, 256>>>(deg, dinv);
    k_enorm<<<(NE + 255) / 256, 256>>>(row, col, dinv, nrm);

    auto agg = [&](const float* src, float* dst, int F) {
        long tot = (long)NN * F;
        k_aggself<<<(int)((tot + 255) / 256), 256>>>(src, dst, dinv, tot, F);
        k_aggedge<<<(NE + 7) / 8, 256>>>(src, dst, row, col, nrm, F);
    };
    auto gemm = [&](const float* Ain, const float* Win, const float* bias, float* C,
                    int M, int Nn, int K, int relu) {
        dim3 gr(Nn / 128, (M + 127) / 128);
        k_gemm_tf32x3<<<gr, 256>>>(Ain, Win, bias, C, M, Nn, K, relu);
    };
    auto bn = [&](float* X, const float* bias, const float* gm, const float* bt, int F) {
        dim3 gr((F + 31) / 32, BN_CHUNKS);
        k_bnpart<<<gr, 256>>>(X, bias, NN, F, ps, pq);
        k_bnfin<<<(F + 127) / 128, 128>>>(ps, pq, F, BN_CHUNKS, mean, rstd);
        long tot = (long)NN * F;
        k_bnapply<<<(int)((tot + 255) / 256), 256>>>(X, bias, gm, bt, mean, rstd, tot, F);
    };

    // Layer 1 (29 -> 1024): aggregate first (29 feats), then GEMM(+b,relu), BN
    agg(x, A, 29);
    gemm(A, W[0], b[0], B, NN, 1024, 29, 1);
    bn(B, nullptr, g[0], be[0], 1024);

    // Layer 2 (1024 -> 512): GEMM first, aggregate on 512, then b+relu+BN fused
    gemm(B, W[1], nullptr, A, NN, 512, 1024, 0);
    agg(A, B, 512);
    bn(B, b[1], g[1], be[1], 512);

    // Layer 3 (512 -> 256): GEMM first, aggregate on 256
    gemm(B, W[2], nullptr, A, NN, 256, 512, 0);
    agg(A, B, 256);
    bn(B, b[2], g[2], be[2], 256);

    // Layer 4 (256 -> 512): aggregate first (256), GEMM(+b,relu), BN
    agg(B, A, 256);
    gemm(A, W[3], b[3], B, NN, 512, 256, 1);
    bn(B, nullptr, g[3], be[3], 512);

    // Layer 5 (512 -> 1024): aggregate first (512), GEMM(+b,relu), BN
    agg(B, A, 512);
    gemm(A, W[4], b[4], B, NN, 1024, 512, 1);
    bn(B, nullptr, g[4], be[4], 1024);

    // ---- global attention pooling ----
    k_gate<<<(NN * 32 + 255) / 256, 256>>>(B, Wg, bg, gate);
    k_fill<<<(NG + 255) / 256, 256>>>(gmax, NG, -3e38f);
    k_fill<<<(NG + 255) / 256, 256>>>(gsum, NG, 0.0f);
    k_segmax<<<(NN + 255) / 256, 256>>>(gate, batch, gmax);
    k_exps<<<(NN + 255) / 256, 256>>>(gate, batch, gmax, gsum);
    k_coef<<<(NN + 255) / 256, 256>>>(gate, batch, gsum);
    k_fill<<<(NG * 1024 + 255) / 256, 256>>>(pool, (long)NG * 1024, 0.0f);
    k_pool<<<(int)(((long)NN * 1024 + 255) / 256), 256>>>(B, gate, batch, pool);

    // ---- MLP head ----
    k_mlp<<<(NG * 128 + 255) / 256, 256>>>(pool, Wf2, bf2, p2, NG, 128, 1024, 1);
    k_mlp<<<(NG * 16 + 255) / 256, 256>>>(p2, Wf3, bf3, p3, NG, 16, 128, 1);
    k_mlp<<<(NG + 255) / 256, 256>>>(p3, Wf4, bf4, (float*)d_out, NG, 1, 16, 0);
}